// round 15
// baseline (speedup 1.0000x reference)
#include <cuda_runtime.h>
#include <math.h>
#include <stdint.h>

#define NUM_ITEMS  10000
#define NUM_USERS  10000
#define NUM_GROUPS 5000
#define EMB_DIM    64
#define BATCH      16384
#define NCOLS      10000

#define WCAP   512            // k1 per-warp hit-index buffer (>= max hits per 2KB block)
#define BLKF4  128            // float4 per cp.async stream block (2 KB)
#define GCAP   320            // CSR capacity per gu row (mean ~100, 20+ sigma margin)
#define PROJ_BLOCKS 80        // item-projection blocks appended to fused grid

// Scratch (allocation-free rule: __device__ globals)
__device__ float    g_user_embeds[NUM_USERS * EMB_DIM];    // divided (clamped cnt)
__device__ float    g_hi[NUM_ITEMS * 8];                   // item_emb @ W1_bot
__device__ float    g_hg[NUM_GROUPS * 8];                  // ge @ W1_top + b1
__device__ uint16_t g_gcsr[NUM_GROUPS * GCAP];             // gu hit indices
__device__ int      g_gcnt[NUM_GROUPS];                    // gu hit counts

// ---- cp.async helpers -----------------------------------------------------
__device__ __forceinline__ void cp_async16(void* smem, const void* gmem) {
    unsigned saddr = (unsigned)__cvta_generic_to_shared(smem);
    asm volatile("cp.async.cg.shared.global [%0], [%1], 16;"
                 :: "r"(saddr), "l"(gmem));
}
#define CP_COMMIT()  asm volatile("cp.async.commit_group;" ::: "memory")
#define CP_WAIT(n)   asm volatile("cp.async.wait_group %0;" :: "n"(n) : "memory")

// ---- byte-pack detection: entries are exactly {0.0f,1.0f}; byte3==0x3F iff 1
__device__ __forceinline__ unsigned detect4(float4 v) {
    const unsigned p = __byte_perm(__float_as_uint(v.x), __float_as_uint(v.y), 0x0073) |
                       __byte_perm(__float_as_uint(v.z), __float_as_uint(v.w), 0x7300);
    return p & 0x01010101u;
}

// ---- project a per-lane float2 slice against W1 rows [rbase+2*lane, +1],
//      butterfly-reduce, write h[0..7] to dst (+ optional bias add).
__device__ __forceinline__ void project_and_store(float ex, float ey, int rbase,
                                                  const float* __restrict__ W1,
                                                  const float* __restrict__ bias,
                                                  float* __restrict__ dst, int lane)
{
    float h[8];
    const float* w0 = W1 + (rbase + 2 * lane) * 8;
    #pragma unroll
    for (int k = 0; k < 8; ++k)
        h[k] = ex * __ldg(&w0[k]) + ey * __ldg(&w0[8 + k]);
    #pragma unroll
    for (int k = 0; k < 8; ++k) {
        #pragma unroll
        for (int d = 16; d; d >>= 1)
            h[k] += __shfl_xor_sync(0xffffffffu, h[k], d);
    }
    #pragma unroll
    for (int k = 0; k < 8; ++k)
        if (lane == k) dst[k] = h[k] + (bias ? __ldg(&bias[k]) : 0.f);
}

// ---------------------------------------------------------------------------
// Batched gather from idx list in smem: 8 indep LDG.64 in flight,
// double-buffered so one L2 latency is exposed per flush.
// ---------------------------------------------------------------------------
__device__ __forceinline__ void load_batch(const int* __restrict__ idxbuf, int j,
                                           int lane, const float2* __restrict__ emb2,
                                           float2* e)
{
    int id[8];
    #pragma unroll
    for (int t = 0; t < 8; ++t) id[t] = idxbuf[j + t];
    #pragma unroll
    for (int t = 0; t < 8; ++t) e[t] = emb2[id[t] * 32 + lane];
}

__device__ __forceinline__ void gather_accumulate(const int* __restrict__ idxbuf,
                                                  int nh, int lane,
                                                  const float2* __restrict__ emb2,
                                                  float2& acc)
{
    const int nfull = nh & ~7;
    if (nfull) {
        float2 ea[8];
        load_batch(idxbuf, 0, lane, emb2, ea);
        for (int j = 8; j < nfull; j += 8) {
            float2 eb[8];
            load_batch(idxbuf, j, lane, emb2, eb);
            #pragma unroll
            for (int t = 0; t < 8; ++t) { acc.x += ea[t].x; acc.y += ea[t].y; }
            #pragma unroll
            for (int t = 0; t < 8; ++t) ea[t] = eb[t];
        }
        #pragma unroll
        for (int t = 0; t < 8; ++t) { acc.x += ea[t].x; acc.y += ea[t].y; }
    }
    for (int j = nfull; j < nh; ++j) {
        const float2 e = emb2[idxbuf[j] * 32 + lane];
        acc.x += e.x; acc.y += e.y;
    }
}

// ---------------------------------------------------------------------------
// FUSED kernel: 3750 role blocks + 80 item-projection blocks.
//   role k1  (2 of 3): ui row scan via cp.async stage + smem idx buffer +
//                      deferred batched gather of item_emb -> user_embeds.
//   role scan(1 of 3): gu row pure stream -> uint16 CSR hit list + count.
//   role proj (blocks >= 3750): h_i[item] = item_emb[item] @ W1_bot
//                               (independent of everything; wave-slack free).
// ---------------------------------------------------------------------------
__global__ __launch_bounds__(128, 9)
void fused_kernel(const float* __restrict__ ui,
                  const float* __restrict__ gu,
                  const float* __restrict__ item_emb,
                  const float* __restrict__ W1)
{
    __shared__ float4 s_stage[4][2][BLKF4];       // 16 KB (k1 role)
    __shared__ int    s_idx[4][WCAP];             // 8 KB  (k1 role)
    __shared__ int    s_nh[4];

    const int lane = threadIdx.x & 31;
    const int wl   = threadIdx.x >> 5;
    const int b    = blockIdx.x;

    if (b >= 3750) {
        // ================= proj role: item projections =================
        const int w = (b - 3750) * 4 + wl;        // 0..319
        const float2* __restrict__ ie2 = (const float2*)item_emb;
        for (int it = w; it < NUM_ITEMS; it += PROJ_BLOCKS * 4) {
            const float2 e = ie2[(size_t)it * 32 + lane];
            project_and_store(e.x, e.y, EMB_DIM, W1, nullptr,
                              g_hi + (size_t)it * 8, lane);
        }
        return;
    }

    const int r = b % 3;
    const int q = b / 3;                          // 0..1249

    if (lane == 0) s_nh[wl] = 0;
    __syncwarp();

    if (r == 2) {
        // ================= scan role: gu row -> CSR =================
        const int row = q * 4 + wl;               // 0..4999
        const float4* __restrict__ row4 = (const float4*)(gu + (size_t)row * NCOLS);
        const int ncols4 = NCOLS / 4;             // 2500
        uint16_t* __restrict__ csr = g_gcsr + (size_t)row * GCAP;

        for (int base = 0; base < ncols4; base += 256) {
            float4 v[8];
            #pragma unroll
            for (int u = 0; u < 8; ++u) {
                const int jj = base + u * 32 + lane;
                v[u] = (jj < ncols4) ? __ldcs(&row4[jj])
                                     : make_float4(0.f, 0.f, 0.f, 0.f);
            }
            unsigned br[8];
            unsigned ucnt = 0u;
            #pragma unroll
            for (int u = 0; u < 8; ++u) {
                br[u] = detect4(v[u]);
                ucnt = __dp4a(br[u], 0x01010101u, ucnt);
            }
            int off = atomicAdd(&s_nh[wl], (int)ucnt);
            const int ebase = base * 4 + lane * 4;
            #pragma unroll
            for (int u = 0; u < 8; ++u) {
                unsigned bm = br[u];
                while (bm) {
                    const int k = __ffs(bm) - 1;
                    bm &= bm - 1;
                    if (off < GCAP)
                        csr[off] = (uint16_t)(ebase + u * 128 + (k >> 3));
                    ++off;
                }
            }
        }
        __syncwarp();
        if (lane == 0) g_gcnt[row] = s_nh[wl];
        return;
    }

    // ================= k1 role: ui row -> user_embeds =================
    const int row = (q * 2 + r) * 4 + wl;         // 0..9999
    const int ncols4 = NCOLS / 4;
    const int nblk   = (ncols4 + BLKF4 - 1) / BLKF4;
    const float4* __restrict__ row4 = (const float4*)(ui + (size_t)row * NCOLS);
    const float2* __restrict__ emb2 = (const float2*)item_emb;
    int* idxbuf = s_idx[wl];

    float2 acc = make_float2(0.f, 0.f);
    int nh = 0, tot = 0;

    {   // prologue: stage block 0
        #pragma unroll
        for (int u = 0; u < 4; ++u) {
            const int jj = u * 32 + lane;
            if (jj < ncols4) cp_async16(&s_stage[wl][0][u * 32 + lane], &row4[jj]);
        }
        CP_COMMIT();
    }

    for (int bb = 0; bb < nblk; ++bb) {
        if (bb + 1 < nblk) {
            const int nb = (bb + 1) * BLKF4;
            #pragma unroll
            for (int u = 0; u < 4; ++u) {
                const int jj = nb + u * 32 + lane;
                if (jj < ncols4)
                    cp_async16(&s_stage[wl][(bb + 1) & 1][u * 32 + lane], &row4[jj]);
            }
        }
        CP_COMMIT();
        CP_WAIT(1);

        const int base = bb * BLKF4;
        const float4* stage = s_stage[wl][bb & 1];
        unsigned br[4];
        unsigned ucnt = 0u;
        #pragma unroll
        for (int u = 0; u < 4; ++u) {
            const int jj = base + u * 32 + lane;
            float4 v = (jj < ncols4) ? stage[u * 32 + lane]
                                     : make_float4(0.f, 0.f, 0.f, 0.f);
            br[u] = detect4(v);
            ucnt = __dp4a(br[u], 0x01010101u, ucnt);
        }
        const int cnt  = (int)ucnt;
        const int btot = __reduce_add_sync(0xffffffffu, cnt);
        if (nh + btot > WCAP) {
            __syncwarp();
            gather_accumulate(idxbuf, nh, lane, emb2, acc);
            tot += nh; nh = 0;
            if (lane == 0) s_nh[wl] = 0;
            __syncwarp();
        }
        int off = atomicAdd(&s_nh[wl], cnt);
        const int ebase = base * 4 + lane * 4;
        #pragma unroll
        for (int u = 0; u < 4; ++u) {
            unsigned bm = br[u];
            while (bm) {
                const int k = __ffs(bm) - 1;
                bm &= bm - 1;
                idxbuf[off++] = ebase + u * 128 + (k >> 3);
            }
        }
        nh += btot;
        __syncwarp();
    }
    CP_WAIT(0);

    gather_accumulate(idxbuf, nh, lane, emb2, acc);
    tot += nh;

    const float inv = 1.0f / fmaxf((float)tot, 1.0f);   // clamped divisor (k1)
    float2* __restrict__ out2 = (float2*)(g_user_embeds + (size_t)row * EMB_DIM);
    out2[lane] = make_float2(acc.x * inv, acc.y * inv);
}

// ---------------------------------------------------------------------------
// Group gather (R12 measured-best form): one warp per group; float2 batched
// double-buffered gather of user_embeds rows from CSR. Epilogue projects the
// group embedding through W1_top (+b1) -> g_hg (group_embeds never written).
// Raw-count divisor (>=1 guaranteed). Slow path rescans gu if CSR overflowed.
// ---------------------------------------------------------------------------
__global__ __launch_bounds__(128)
void group_gather_kernel(const float* __restrict__ gu,
                         const float* __restrict__ W1,
                         const float* __restrict__ b1)
{
    const int lane = threadIdx.x & 31;
    const int wl   = threadIdx.x >> 5;
    const int row  = blockIdx.x * 4 + wl;
    if (row >= NUM_GROUPS) return;

    const float2* __restrict__ ue2 = (const float2*)g_user_embeds;
    const int cnt = g_gcnt[row];
    float2 acc = make_float2(0.f, 0.f);

    if (cnt <= GCAP) {
        const uint16_t* __restrict__ csr = g_gcsr + (size_t)row * GCAP;
        const int nfull = cnt & ~7;
        if (nfull) {
            float2 ea[8];
            int id[8];
            #pragma unroll
            for (int t = 0; t < 8; ++t) id[t] = csr[t];
            #pragma unroll
            for (int t = 0; t < 8; ++t) ea[t] = ue2[id[t] * 32 + lane];
            for (int j = 8; j < nfull; j += 8) {
                float2 eb[8];
                #pragma unroll
                for (int t = 0; t < 8; ++t) id[t] = csr[j + t];
                #pragma unroll
                for (int t = 0; t < 8; ++t) eb[t] = ue2[id[t] * 32 + lane];
                #pragma unroll
                for (int t = 0; t < 8; ++t) { acc.x += ea[t].x; acc.y += ea[t].y; }
                #pragma unroll
                for (int t = 0; t < 8; ++t) ea[t] = eb[t];
            }
            #pragma unroll
            for (int t = 0; t < 8; ++t) { acc.x += ea[t].x; acc.y += ea[t].y; }
        }
        for (int j = nfull; j < cnt; ++j) {
            const float2 e = ue2[(int)csr[j] * 32 + lane];
            acc.x += e.x; acc.y += e.y;
        }
    } else {
        // slow path: rescan the gu row inline (never expected)
        const float4* __restrict__ row4 = (const float4*)(gu + (size_t)row * NCOLS);
        for (int base = 0; base < NCOLS / 4; base += 32) {
            const int j4 = base + lane;
            float4 v = (j4 < NCOLS / 4) ? row4[j4] : make_float4(0.f, 0.f, 0.f, 0.f);
            #pragma unroll
            for (int c = 0; c < 4; ++c) {
                unsigned m = __ballot_sync(0xffffffffu, (&v.x)[c] > 0.f);
                while (m) {
                    const int l = __ffs(m) - 1;
                    m &= m - 1;
                    const float2 e = ue2[((base + l) * 4 + c) * 32 + lane];
                    acc.x += e.x; acc.y += e.y;
                }
            }
        }
    }

    // epilogue: normalize + project through W1_top (+b1) -> g_hg[row]
    const float inv = 1.0f / (float)cnt;          // raw divisor, no clamp
    project_and_store(acc.x * inv, acc.y * inv, 0, W1, b1,
                      g_hg + (size_t)row * 8, lane);
}

// ---------------------------------------------------------------------------
// Micro-MLP: y = sigmoid(b2 + sum_k relu(hg[g][k] + hi[it][k]) * W2[k])
// ---------------------------------------------------------------------------
__global__ __launch_bounds__(256)
void final_kernel(const float* __restrict__ W2,
                  const float* __restrict__ b2,
                  const int*   __restrict__ gidx,
                  const int*   __restrict__ iidx,
                  float* __restrict__ out)
{
    __shared__ float sW2[8];
    __shared__ float sb2;
    if (threadIdx.x < 8) sW2[threadIdx.x] = W2[threadIdx.x];
    if (threadIdx.x == 0) sb2 = b2[0];
    __syncthreads();

    const int i = blockIdx.x * 256 + threadIdx.x;
    if (i >= BATCH) return;

    const float4* hg = (const float4*)(g_hg + (size_t)gidx[i] * 8);
    const float4* hi = (const float4*)(g_hi + (size_t)iidx[i] * 8);
    const float4 a0 = hg[0], a1 = hg[1];
    const float4 c0 = hi[0], c1 = hi[1];

    float y = sb2;
    y += fmaxf(a0.x + c0.x, 0.f) * sW2[0];
    y += fmaxf(a0.y + c0.y, 0.f) * sW2[1];
    y += fmaxf(a0.z + c0.z, 0.f) * sW2[2];
    y += fmaxf(a0.w + c0.w, 0.f) * sW2[3];
    y += fmaxf(a1.x + c1.x, 0.f) * sW2[4];
    y += fmaxf(a1.y + c1.y, 0.f) * sW2[5];
    y += fmaxf(a1.z + c1.z, 0.f) * sW2[6];
    y += fmaxf(a1.w + c1.w, 0.f) * sW2[7];

    out[i] = 1.0f / (1.0f + expf(-y));
}

// ---------------------------------------------------------------------------
extern "C" void kernel_launch(void* const* d_in, const int* in_sizes, int n_in,
                              void* d_out, int out_size)
{
    const float* item_emb = (const float*)d_in[0];
    const float* ui       = (const float*)d_in[1];
    const float* gu       = (const float*)d_in[2];
    const float* W1       = (const float*)d_in[3];
    const float* b1       = (const float*)d_in[4];
    const float* W2       = (const float*)d_in[5];
    const float* b2       = (const float*)d_in[6];
    const int*   gidx     = (const int*)d_in[7];
    const int*   iidx     = (const int*)d_in[8];
    float* out            = (float*)d_out;

    // 1) fused: k1 (ui scan+gather -> user_embeds) || gu scan -> CSR
    //           || item projections -> g_hi (free wave slack)
    fused_kernel<<<3750 + PROJ_BLOCKS, 128>>>(ui, gu, item_emb, W1);

    // 2) group gather from CSR + projection epilogue -> g_hg
    group_gather_kernel<<<1250, 128>>>(gu, W1, b1);

    // 3) micro-MLP head
    final_kernel<<<(BATCH + 255) / 256, 256>>>(W2, b2, gidx, iidx, out);
}